// round 1
// baseline (speedup 1.0000x reference)
#include <cuda_runtime.h>
#include <math.h>

// Transformer block: B=4096, T=64, C=64, H=4, hd=16.
// One CTA per batch element. All activations resident in SMEM.
// fp32 everywhere (matches reference bit-for-bit up to reassociation).

#define T_DIM 64
#define C_DIM 64
#define NHEAD 4
#define HDIM  16
#define EPS   1e-5f

// dynamic smem layout (floats):
//   sX  [64*64]   residual stream (x, then x1)
//   sH  [64*64]   layernorm output (ln1 then ln2)
//   sU  [64*256]  union: qkv [64*192] during attn, fc-act [64*256] during MLP
//   sY  [64*64]   attention output
#define SMEM_FLOATS (4096 + 4096 + 16384 + 4096)
#define SMEM_BYTES  (SMEM_FLOATS * 4)

__device__ __forceinline__ void layer_norm_64(
    const float* __restrict__ src, float* __restrict__ dst,
    const float* __restrict__ g, const float* __restrict__ bta,
    int lane, int warp)
{
    // each warp handles tokens warp, warp+8, ... (8 tokens per warp)
    float g0 = g[lane],      g1 = g[lane + 32];
    float b0 = bta[lane],    b1 = bta[lane + 32];
    for (int t = warp; t < T_DIM; t += 8) {
        float v0 = src[t * 64 + lane];
        float v1 = src[t * 64 + lane + 32];
        float s = v0 + v1;
        #pragma unroll
        for (int off = 16; off > 0; off >>= 1) s += __shfl_xor_sync(0xffffffffu, s, off);
        float mu = s * (1.0f / 64.0f);
        float d0 = v0 - mu, d1 = v1 - mu;
        float vs = d0 * d0 + d1 * d1;
        #pragma unroll
        for (int off = 16; off > 0; off >>= 1) vs += __shfl_xor_sync(0xffffffffu, vs, off);
        float r = rsqrtf(vs * (1.0f / 64.0f) + EPS);
        dst[t * 64 + lane]      = d0 * r * g0 + b0;
        dst[t * 64 + lane + 32] = d1 * r * g1 + b1;
    }
}

__global__ __launch_bounds__(256) void block_kernel(
    const float* __restrict__ x,
    const float* __restrict__ ln1_g, const float* __restrict__ ln1_b,
    const float* __restrict__ qkv_w, const float* __restrict__ qkv_b,
    const float* __restrict__ proj_w, const float* __restrict__ proj_b,
    const float* __restrict__ ln2_g, const float* __restrict__ ln2_b,
    const float* __restrict__ fc_w, const float* __restrict__ fc_b,
    const float* __restrict__ p2_w, const float* __restrict__ p2_b,
    float* __restrict__ out)
{
    extern __shared__ float smem[];
    float* sX = smem;            // 64x64
    float* sH = sX + 4096;       // 64x64
    float* sU = sH + 4096;       // 64x256 (qkv: 64x192)
    float* sY = sU + 16384;      // 64x64

    const int b    = blockIdx.x;
    const int tid  = threadIdx.x;
    const int lane = tid & 31;
    const int warp = tid >> 5;

    // ---- load x tile ----
    {
        const float4* xg = (const float4*)(x + (size_t)b * 4096);
        float4* s4 = (float4*)sX;
        #pragma unroll
        for (int idx = tid; idx < 1024; idx += 256) s4[idx] = xg[idx];
    }
    __syncthreads();

    // ---- LN1 ----
    layer_norm_64(sX, sH, ln1_g, ln1_b, lane, warp);
    __syncthreads();

    // ---- qkv GEMM: [64,64] @ [64,192] -> sU[64,192] ----
    // microtile: 4 tokens x 8 cols; 16 tg x 24 cg = 384 tasks over 2 iters
    #pragma unroll
    for (int it = 0; it < 2; ++it) {
        int task = it * 256 + tid;
        if (task < 384) {
            int cg = task % 24, tg = task / 24;
            int t0 = tg * 4, j0 = cg * 8;
            float acc[4][8];
            #pragma unroll
            for (int m = 0; m < 4; ++m)
                #pragma unroll
                for (int n = 0; n < 8; ++n) acc[m][n] = 0.0f;
            #pragma unroll 4
            for (int k = 0; k < 64; ++k) {
                float4 w0 = *(const float4*)&qkv_w[k * 192 + j0];
                float4 w1 = *(const float4*)&qkv_w[k * 192 + j0 + 4];
                float wv[8] = {w0.x, w0.y, w0.z, w0.w, w1.x, w1.y, w1.z, w1.w};
                #pragma unroll
                for (int m = 0; m < 4; ++m) {
                    float hv = sH[(t0 + m) * 64 + k];
                    #pragma unroll
                    for (int n = 0; n < 8; ++n) acc[m][n] += hv * wv[n];
                }
            }
            float4 bb0 = *(const float4*)&qkv_b[j0];
            float4 bb1 = *(const float4*)&qkv_b[j0 + 4];
            float bv[8] = {bb0.x, bb0.y, bb0.z, bb0.w, bb1.x, bb1.y, bb1.z, bb1.w};
            #pragma unroll
            for (int m = 0; m < 4; ++m)
                #pragma unroll
                for (int n = 0; n < 8; ++n)
                    sU[(t0 + m) * 192 + j0 + n] = acc[m][n] + bv[n];
        }
    }
    __syncthreads();

    // ---- attention: one thread per (head, query) ----
    {
        int h = tid >> 6;          // 0..3
        int i = tid & 63;          // query index
        const int qo = h * HDIM;
        float q[HDIM];
        #pragma unroll
        for (int d = 0; d < HDIM; ++d) q[d] = sU[i * 192 + qo + d];

        // pass 1: row max
        float mmax = -1e30f;
        for (int j = 0; j <= i; ++j) {
            const float* kp = &sU[j * 192 + 64 + qo];
            float s = 0.0f;
            #pragma unroll
            for (int d = 0; d < HDIM; ++d) s += q[d] * kp[d];
            s *= 0.25f;
            mmax = fmaxf(mmax, s);
        }
        // pass 2: sum + weighted V
        float l = 0.0f;
        float y[HDIM];
        #pragma unroll
        for (int d = 0; d < HDIM; ++d) y[d] = 0.0f;
        for (int j = 0; j <= i; ++j) {
            const float* kp = &sU[j * 192 + 64 + qo];
            float s = 0.0f;
            #pragma unroll
            for (int d = 0; d < HDIM; ++d) s += q[d] * kp[d];
            s *= 0.25f;
            float p = __expf(s - mmax);
            l += p;
            const float* vp = &sU[j * 192 + 128 + qo];
            #pragma unroll
            for (int d = 0; d < HDIM; ++d) y[d] += p * vp[d];
        }
        float inv = 1.0f / l;
        #pragma unroll
        for (int d = 0; d < HDIM; ++d) sY[i * 64 + qo + d] = y[d] * inv;
    }
    __syncthreads();

    // ---- proj GEMM + residual: sX += sY @ proj_w + b ----
    // microtile: 2 tokens x 8 cols; 32 tg x 8 cg = 256 tasks
    {
        int cg = tid % 8, tg = tid / 8;
        int t0 = tg * 2, j0 = cg * 8;
        float acc[2][8];
        #pragma unroll
        for (int m = 0; m < 2; ++m)
            #pragma unroll
            for (int n = 0; n < 8; ++n) acc[m][n] = 0.0f;
        #pragma unroll 4
        for (int k = 0; k < 64; ++k) {
            float4 w0 = *(const float4*)&proj_w[k * 64 + j0];
            float4 w1 = *(const float4*)&proj_w[k * 64 + j0 + 4];
            float wv[8] = {w0.x, w0.y, w0.z, w0.w, w1.x, w1.y, w1.z, w1.w};
            #pragma unroll
            for (int m = 0; m < 2; ++m) {
                float yv = sY[(t0 + m) * 64 + k];
                #pragma unroll
                for (int n = 0; n < 8; ++n) acc[m][n] += yv * wv[n];
            }
        }
        float4 bb0 = *(const float4*)&proj_b[j0];
        float4 bb1 = *(const float4*)&proj_b[j0 + 4];
        float bv[8] = {bb0.x, bb0.y, bb0.z, bb0.w, bb1.x, bb1.y, bb1.z, bb1.w};
        #pragma unroll
        for (int m = 0; m < 2; ++m)
            #pragma unroll
            for (int n = 0; n < 8; ++n)
                sX[(t0 + m) * 64 + j0 + n] += acc[m][n] + bv[n];
    }
    __syncthreads();

    // ---- LN2 ----
    layer_norm_64(sX, sH, ln2_g, ln2_b, lane, warp);
    __syncthreads();

    // ---- fc GEMM + GELU: sU[64,256] = gelu(sH @ fc_w + b) ----
    // microtile: 4 tokens x 8 cols; 16 tg x 32 cg = 512 tasks over 2 iters
    #pragma unroll
    for (int it = 0; it < 2; ++it) {
        int task = it * 256 + tid;
        int cg = task % 32, tg = task / 32;
        int t0 = tg * 4, j0 = cg * 8;
        float acc[4][8];
        #pragma unroll
        for (int m = 0; m < 4; ++m)
            #pragma unroll
            for (int n = 0; n < 8; ++n) acc[m][n] = 0.0f;
        #pragma unroll 4
        for (int k = 0; k < 64; ++k) {
            float4 w0 = *(const float4*)&fc_w[k * 256 + j0];
            float4 w1 = *(const float4*)&fc_w[k * 256 + j0 + 4];
            float wv[8] = {w0.x, w0.y, w0.z, w0.w, w1.x, w1.y, w1.z, w1.w};
            #pragma unroll
            for (int m = 0; m < 4; ++m) {
                float hv = sH[(t0 + m) * 64 + k];
                #pragma unroll
                for (int n = 0; n < 8; ++n) acc[m][n] += hv * wv[n];
            }
        }
        float4 bb0 = *(const float4*)&fc_b[j0];
        float4 bb1 = *(const float4*)&fc_b[j0 + 4];
        float bv[8] = {bb0.x, bb0.y, bb0.z, bb0.w, bb1.x, bb1.y, bb1.z, bb1.w};
        #pragma unroll
        for (int m = 0; m < 4; ++m)
            #pragma unroll
            for (int n = 0; n < 8; ++n) {
                float v = acc[m][n] + bv[n];
                // exact gelu: 0.5*v*(1+erf(v/sqrt(2)))
                sU[(t0 + m) * 256 + j0 + n] =
                    0.5f * v * (1.0f + erff(v * 0.70710678118654752f));
            }
    }
    __syncthreads();

    // ---- proj2 GEMM + residual -> out ----
    // microtile: 2 tokens x 8 cols; 32 tg x 8 cg = 256 tasks, K=256
    {
        int cg = tid % 8, tg = tid / 8;
        int t0 = tg * 2, j0 = cg * 8;
        float acc[2][8];
        #pragma unroll
        for (int m = 0; m < 2; ++m)
            #pragma unroll
            for (int n = 0; n < 8; ++n) acc[m][n] = 0.0f;
        #pragma unroll 4
        for (int k = 0; k < 256; ++k) {
            float4 w0 = *(const float4*)&p2_w[k * 64 + j0];
            float4 w1 = *(const float4*)&p2_w[k * 64 + j0 + 4];
            float wv[8] = {w0.x, w0.y, w0.z, w0.w, w1.x, w1.y, w1.z, w1.w};
            #pragma unroll
            for (int m = 0; m < 2; ++m) {
                float uv = sU[(t0 + m) * 256 + k];
                #pragma unroll
                for (int n = 0; n < 8; ++n) acc[m][n] += uv * wv[n];
            }
        }
        float4 bb0 = *(const float4*)&p2_b[j0];
        float4 bb1 = *(const float4*)&p2_b[j0 + 4];
        float bv[8] = {bb0.x, bb0.y, bb0.z, bb0.w, bb1.x, bb1.y, bb1.z, bb1.w};
        float* og = out + (size_t)b * 4096;
        #pragma unroll
        for (int m = 0; m < 2; ++m) {
            int t = t0 + m;
            float4 o0, o1;
            o0.x = sX[t * 64 + j0 + 0] + acc[m][0] + bv[0];
            o0.y = sX[t * 64 + j0 + 1] + acc[m][1] + bv[1];
            o0.z = sX[t * 64 + j0 + 2] + acc[m][2] + bv[2];
            o0.w = sX[t * 64 + j0 + 3] + acc[m][3] + bv[3];
            o1.x = sX[t * 64 + j0 + 4] + acc[m][4] + bv[4];
            o1.y = sX[t * 64 + j0 + 5] + acc[m][5] + bv[5];
            o1.z = sX[t * 64 + j0 + 6] + acc[m][6] + bv[6];
            o1.w = sX[t * 64 + j0 + 7] + acc[m][7] + bv[7];
            *(float4*)&og[t * 64 + j0]     = o0;
            *(float4*)&og[t * 64 + j0 + 4] = o1;
        }
    }
}

extern "C" void kernel_launch(void* const* d_in, const int* in_sizes, int n_in,
                              void* d_out, int out_size)
{
    const float* x      = (const float*)d_in[0];
    const float* ln1_g  = (const float*)d_in[1];
    const float* ln1_b  = (const float*)d_in[2];
    const float* qkv_w  = (const float*)d_in[3];
    const float* qkv_b  = (const float*)d_in[4];
    const float* proj_w = (const float*)d_in[5];
    const float* proj_b = (const float*)d_in[6];
    const float* ln2_g  = (const float*)d_in[7];
    const float* ln2_b  = (const float*)d_in[8];
    const float* fc_w   = (const float*)d_in[9];
    const float* fc_b   = (const float*)d_in[10];
    const float* p2_w   = (const float*)d_in[11];
    const float* p2_b   = (const float*)d_in[12];
    float* out = (float*)d_out;

    int B = in_sizes[0] / (T_DIM * C_DIM);   // 4096

    cudaFuncSetAttribute(block_kernel,
                         cudaFuncAttributeMaxDynamicSharedMemorySize, SMEM_BYTES);

    block_kernel<<<B, 256, SMEM_BYTES>>>(
        x, ln1_g, ln1_b, qkv_w, qkv_b, proj_w, proj_b,
        ln2_g, ln2_b, fc_w, fc_b, p2_w, p2_b, out);
}

// round 2
// speedup vs baseline: 6.2247x; 6.2247x over previous
#include <cuda_runtime.h>
#include <cuda_bf16.h>
#include <math.h>
#include <stdint.h>

// Transformer block B=4096, T=64, C=64, H=4, hd=16.
// bf16 mma.sync tensor-core path, fp32 LN/softmax/gelu/residual.

#define EPS 1e-5f

// ---- fragment-ordered weight buffer (bf16), filled by pre-kernel ----
// frag = 32 lanes x uint2 (2 b32 regs of 2 bf16 each), mma.m16n8k16 B layout
#define F_QKV  0      // 24 nb * 4 kb  = 96
#define F_PROJ 96     //  8 * 4        = 32
#define F_FC   128    // 32 * 4        = 128
#define F_P2   256    //  8 * 16       = 128
#define N_FRAGS 384
__device__ uint2 g_wfrag[N_FRAGS * 32];

__global__ void convert_weights(const float* __restrict__ qkv_w,
                                const float* __restrict__ proj_w,
                                const float* __restrict__ fc_w,
                                const float* __restrict__ p2_w)
{
    int e = blockIdx.x * blockDim.x + threadIdx.x;
    const float* W; int K, N, base;
    if (e < 12288)      { W = qkv_w;  K = 64;  N = 192; base = F_QKV; }
    else if (e < 16384) { W = proj_w; K = 64;  N = 64;  base = F_PROJ; e -= 12288; }
    else if (e < 32768) { W = fc_w;   K = 64;  N = 256; base = F_FC;   e -= 16384; }
    else if (e < 49152) { W = p2_w;   K = 256; N = 64;  base = F_P2;   e -= 32768; }
    else return;
    int k = e / N, n = e % N;
    int nb = n >> 3, kb = k >> 4, kr = k & 15;
    int lane = (n & 7) * 4 + ((kr & 7) >> 1);
    int reg  = kr >> 3;
    int half = kr & 1;
    int KB = K >> 4;
    __nv_bfloat16 v = __float2bfloat16(W[k * N + n]);
    unsigned short* dst = (unsigned short*)g_wfrag;
    dst[(((base + nb * KB + kb) * 32 + lane) * 2 + reg) * 2 + half] =
        *(unsigned short*)&v;
}

// ---- helpers ----
__device__ __forceinline__ void mma16816(float c[4],
    uint32_t a0, uint32_t a1, uint32_t a2, uint32_t a3,
    uint32_t b0, uint32_t b1)
{
    asm volatile(
        "mma.sync.aligned.m16n8k16.row.col.f32.bf16.bf16.f32 "
        "{%0,%1,%2,%3}, {%4,%5,%6,%7}, {%8,%9}, {%0,%1,%2,%3};\n"
        : "+f"(c[0]), "+f"(c[1]), "+f"(c[2]), "+f"(c[3])
        : "r"(a0), "r"(a1), "r"(a2), "r"(a3), "r"(b0), "r"(b1));
}

__device__ __forceinline__ uint32_t pack_bf16(float lo, float hi) {
    __nv_bfloat162 h = __floats2bfloat162_rn(lo, hi);
    return *(uint32_t*)&h;
}
__device__ __forceinline__ uint32_t pack2(__nv_bfloat16 lo, __nv_bfloat16 hi) {
    return (uint32_t)(*(unsigned short*)&lo) |
           ((uint32_t)(*(unsigned short*)&hi) << 16);
}
__device__ __forceinline__ float gelu_exact(float v) {
    return 0.5f * v * (1.0f + erff(v * 0.70710678118654752f));
}

// layernorm of fp32 [64x64] -> bf16 [64 x stride72]
__device__ __forceinline__ void layer_norm_bf16(
    const float* __restrict__ src, __nv_bfloat16* __restrict__ dst,
    const float* __restrict__ g, const float* __restrict__ bb,
    int lane, int warp)
{
    float g0 = g[lane], g1 = g[lane + 32];
    float b0 = bb[lane], b1 = bb[lane + 32];
    for (int t = warp; t < 64; t += 8) {
        float v0 = src[t * 64 + lane];
        float v1 = src[t * 64 + lane + 32];
        float s = v0 + v1;
        #pragma unroll
        for (int o = 16; o > 0; o >>= 1) s += __shfl_xor_sync(0xffffffffu, s, o);
        float mu = s * (1.0f / 64.0f);
        float d0 = v0 - mu, d1 = v1 - mu;
        float vs = d0 * d0 + d1 * d1;
        #pragma unroll
        for (int o = 16; o > 0; o >>= 1) vs += __shfl_xor_sync(0xffffffffu, vs, o);
        float rr = rsqrtf(vs * (1.0f / 64.0f) + EPS);
        dst[t * 72 + lane]      = __float2bfloat16(d0 * rr * g0 + b0);
        dst[t * 72 + lane + 32] = __float2bfloat16(d1 * rr * g1 + b1);
    }
}

// SMEM layout (bytes):
//   sXf  fp32 [64*64]                    @ 0      (16384)
//   sU   bf16 union:                     @ 16384  (33792)
//        qkv [64 x 200]  (stride 200 bf16 = 100 words)
//        gelu [64 x 264] (stride 264 bf16 = 132 words)
//   sA   bf16 [64 x 72]                  @ 50176  (9216)   LN output
//   sY   bf16 [64 x 72]                  @ 59392  (9216)   attn output
#define SMEM_BYTES 68608

__global__ __launch_bounds__(256) void block_kernel(
    const float* __restrict__ x,
    const float* __restrict__ ln1_g, const float* __restrict__ ln1_b,
    const float* __restrict__ qkv_b, const float* __restrict__ proj_b,
    const float* __restrict__ ln2_g, const float* __restrict__ ln2_b,
    const float* __restrict__ fc_b,  const float* __restrict__ p2_b,
    float* __restrict__ out)
{
    extern __shared__ char smem[];
    float* sXf = (float*)smem;
    __nv_bfloat16* sU = (__nv_bfloat16*)(smem + 16384);
    __nv_bfloat16* sA = (__nv_bfloat16*)(smem + 50176);
    __nv_bfloat16* sY = (__nv_bfloat16*)(smem + 59392);
    uint32_t* sUw = (uint32_t*)sU;
    uint32_t* sAw = (uint32_t*)sA;
    uint32_t* sYw = (uint32_t*)sY;

    const int b = blockIdx.x, tid = threadIdx.x;
    const int lane = tid & 31, warp = tid >> 5;
    const int r = lane >> 2, q = lane & 3;

    // ---- load x tile ----
    {
        const float4* xg = (const float4*)(x + (size_t)b * 4096);
        float4* s4 = (float4*)sXf;
        #pragma unroll
        for (int i = tid; i < 1024; i += 256) s4[i] = xg[i];
    }
    __syncthreads();

    // ---- LN1: sXf -> sA (bf16) ----
    layer_norm_bf16(sXf, sA, ln1_g, ln1_b, lane, warp);
    __syncthreads();

    // ---- qkv GEMM: sA[64x64] @ W[64x192] + b -> sU qkv (bf16) ----
    #pragma unroll
    for (int s = 0; s < 3; ++s) {
        int nb = warp + s * 8;               // 0..23
        float acc[4][4] = {};
        #pragma unroll
        for (int kb = 0; kb < 4; ++kb) {
            uint2 wb = g_wfrag[(F_QKV + nb * 4 + kb) * 32 + lane];
            #pragma unroll
            for (int mb = 0; mb < 4; ++mb) {
                int row = mb * 16;
                uint32_t a0 = sAw[(row + r)     * 36 + kb * 8 + q];
                uint32_t a1 = sAw[(row + r + 8) * 36 + kb * 8 + q];
                uint32_t a2 = sAw[(row + r)     * 36 + kb * 8 + 4 + q];
                uint32_t a3 = sAw[(row + r + 8) * 36 + kb * 8 + 4 + q];
                mma16816(acc[mb], a0, a1, a2, a3, wb.x, wb.y);
            }
        }
        float bj0 = qkv_b[nb * 8 + 2 * q], bj1 = qkv_b[nb * 8 + 2 * q + 1];
        #pragma unroll
        for (int mb = 0; mb < 4; ++mb) {
            int tok = mb * 16 + r;
            sUw[tok * 100 + nb * 4 + q] =
                pack_bf16(acc[mb][0] + bj0, acc[mb][1] + bj1);
            sUw[(tok + 8) * 100 + nb * 4 + q] =
                pack_bf16(acc[mb][2] + bj0, acc[mb][3] + bj1);
        }
    }
    __syncthreads();

    // ---- attention: 16 row-blocks (h, mb); 2 per warp ----
    for (int blk = warp; blk < 16; blk += 8) {
        int h = blk >> 2, mb = blk & 3;
        int row0 = mb * 16;
        // Q fragment (A operand, 16 queries x 16 dims)
        uint32_t qa0 = sUw[(row0 + r)     * 100 + 8 * h + q];
        uint32_t qa1 = sUw[(row0 + r + 8) * 100 + 8 * h + q];
        uint32_t qa2 = sUw[(row0 + r)     * 100 + 8 * h + 4 + q];
        uint32_t qa3 = sUw[(row0 + r + 8) * 100 + 8 * h + 4 + q];

        float sc[8][4];
        #pragma unroll
        for (int nb = 0; nb < 8; ++nb) {
            sc[nb][0] = sc[nb][1] = sc[nb][2] = sc[nb][3] = 0.0f;
            int tk = nb * 8 + r;             // key token (B col)
            uint32_t kb0 = sUw[tk * 100 + 32 + 8 * h + q];
            uint32_t kb1 = sUw[tk * 100 + 32 + 8 * h + 4 + q];
            mma16816(sc[nb], qa0, qa1, qa2, qa3, kb0, kb1);
        }

        // scale + causal mask + row max (rows r and r+8 of this block)
        int qi0 = row0 + r, qi1 = qi0 + 8;
        float m0 = -1e30f, m1 = -1e30f;
        #pragma unroll
        for (int nb = 0; nb < 8; ++nb)
            #pragma unroll
            for (int cc = 0; cc < 2; ++cc) {
                int kj = nb * 8 + 2 * q + cc;
                float v0 = (kj <= qi0) ? sc[nb][cc] * 0.25f : -1e30f;
                float v1 = (kj <= qi1) ? sc[nb][2 + cc] * 0.25f : -1e30f;
                sc[nb][cc] = v0; sc[nb][2 + cc] = v1;
                m0 = fmaxf(m0, v0); m1 = fmaxf(m1, v1);
            }
        m0 = fmaxf(m0, __shfl_xor_sync(0xffffffffu, m0, 1));
        m0 = fmaxf(m0, __shfl_xor_sync(0xffffffffu, m0, 2));
        m1 = fmaxf(m1, __shfl_xor_sync(0xffffffffu, m1, 1));
        m1 = fmaxf(m1, __shfl_xor_sync(0xffffffffu, m1, 2));

        float l0 = 0.0f, l1 = 0.0f;
        #pragma unroll
        for (int nb = 0; nb < 8; ++nb)
            #pragma unroll
            for (int cc = 0; cc < 2; ++cc) {
                float p0 = __expf(sc[nb][cc] - m0);
                float p1 = __expf(sc[nb][2 + cc] - m1);
                sc[nb][cc] = p0; sc[nb][2 + cc] = p1;
                l0 += p0; l1 += p1;
            }
        l0 += __shfl_xor_sync(0xffffffffu, l0, 1);
        l0 += __shfl_xor_sync(0xffffffffu, l0, 2);
        l1 += __shfl_xor_sync(0xffffffffu, l1, 1);
        l1 += __shfl_xor_sync(0xffffffffu, l1, 2);

        // P (D layout) -> A fragments, in registers
        uint32_t Pf[4][4];
        #pragma unroll
        for (int kb = 0; kb < 4; ++kb) {
            Pf[kb][0] = pack_bf16(sc[2 * kb][0],     sc[2 * kb][1]);
            Pf[kb][1] = pack_bf16(sc[2 * kb][2],     sc[2 * kb][3]);
            Pf[kb][2] = pack_bf16(sc[2 * kb + 1][0], sc[2 * kb + 1][1]);
            Pf[kb][3] = pack_bf16(sc[2 * kb + 1][2], sc[2 * kb + 1][3]);
        }

        // y = P @ V  (unnormalized), N=16 dims as 2 col-blocks
        float y0[4] = {}, y1[4] = {};
        #pragma unroll
        for (int kb = 0; kb < 4; ++kb) {
            int t0 = kb * 16 + 2 * q;
            #pragma unroll
            for (int nbd = 0; nbd < 2; ++nbd) {
                int col = 128 + 16 * h + 8 * nbd + r;   // V column (B col = r)
                uint32_t vb0 = pack2(sU[t0 * 200 + col], sU[(t0 + 1) * 200 + col]);
                uint32_t vb1 = pack2(sU[(t0 + 8) * 200 + col], sU[(t0 + 9) * 200 + col]);
                mma16816(nbd ? y1 : y0, Pf[kb][0], Pf[kb][1], Pf[kb][2], Pf[kb][3],
                         vb0, vb1);
            }
        }
        float inv0 = 1.0f / l0, inv1 = 1.0f / l1;
        int tok = row0 + r;
        sYw[tok * 36 + 8 * h + q]           = pack_bf16(y0[0] * inv0, y0[1] * inv0);
        sYw[(tok + 8) * 36 + 8 * h + q]     = pack_bf16(y0[2] * inv1, y0[3] * inv1);
        sYw[tok * 36 + 8 * h + 4 + q]       = pack_bf16(y1[0] * inv0, y1[1] * inv0);
        sYw[(tok + 8) * 36 + 8 * h + 4 + q] = pack_bf16(y1[2] * inv1, y1[3] * inv1);
    }
    __syncthreads();

    // ---- attn proj + residual: sXf += sY @ W + b ----
    {
        int nb = warp;                        // 0..7
        float acc[4][4] = {};
        #pragma unroll
        for (int kb = 0; kb < 4; ++kb) {
            uint2 wb = g_wfrag[(F_PROJ + nb * 4 + kb) * 32 + lane];
            #pragma unroll
            for (int mb = 0; mb < 4; ++mb) {
                int row = mb * 16;
                uint32_t a0 = sYw[(row + r)     * 36 + kb * 8 + q];
                uint32_t a1 = sYw[(row + r + 8) * 36 + kb * 8 + q];
                uint32_t a2 = sYw[(row + r)     * 36 + kb * 8 + 4 + q];
                uint32_t a3 = sYw[(row + r + 8) * 36 + kb * 8 + 4 + q];
                mma16816(acc[mb], a0, a1, a2, a3, wb.x, wb.y);
            }
        }
        float bj0 = proj_b[nb * 8 + 2 * q], bj1 = proj_b[nb * 8 + 2 * q + 1];
        int j = nb * 8 + 2 * q;
        #pragma unroll
        for (int mb = 0; mb < 4; ++mb) {
            int tok = mb * 16 + r;
            sXf[tok * 64 + j]           += acc[mb][0] + bj0;
            sXf[tok * 64 + j + 1]       += acc[mb][1] + bj1;
            sXf[(tok + 8) * 64 + j]     += acc[mb][2] + bj0;
            sXf[(tok + 8) * 64 + j + 1] += acc[mb][3] + bj1;
        }
    }
    __syncthreads();

    // ---- LN2: sXf -> sA ----
    layer_norm_bf16(sXf, sA, ln2_g, ln2_b, lane, warp);
    __syncthreads();

    // ---- fc GEMM + GELU: sA @ W[64x256] -> sU gelu (bf16, stride 264) ----
    #pragma unroll
    for (int s = 0; s < 4; ++s) {
        int nb = warp + s * 8;               // 0..31
        float acc[4][4] = {};
        #pragma unroll
        for (int kb = 0; kb < 4; ++kb) {
            uint2 wb = g_wfrag[(F_FC + nb * 4 + kb) * 32 + lane];
            #pragma unroll
            for (int mb = 0; mb < 4; ++mb) {
                int row = mb * 16;
                uint32_t a0 = sAw[(row + r)     * 36 + kb * 8 + q];
                uint32_t a1 = sAw[(row + r + 8) * 36 + kb * 8 + q];
                uint32_t a2 = sAw[(row + r)     * 36 + kb * 8 + 4 + q];
                uint32_t a3 = sAw[(row + r + 8) * 36 + kb * 8 + 4 + q];
                mma16816(acc[mb], a0, a1, a2, a3, wb.x, wb.y);
            }
        }
        float bj0 = fc_b[nb * 8 + 2 * q], bj1 = fc_b[nb * 8 + 2 * q + 1];
        #pragma unroll
        for (int mb = 0; mb < 4; ++mb) {
            int tok = mb * 16 + r;
            sUw[tok * 132 + nb * 4 + q] = pack_bf16(
                gelu_exact(acc[mb][0] + bj0), gelu_exact(acc[mb][1] + bj1));
            sUw[(tok + 8) * 132 + nb * 4 + q] = pack_bf16(
                gelu_exact(acc[mb][2] + bj0), gelu_exact(acc[mb][3] + bj1));
        }
    }
    __syncthreads();

    // ---- mlp proj (K=256) + residual -> out ----
    {
        int nb = warp;                        // 0..7
        float acc[4][4] = {};
        #pragma unroll
        for (int kb = 0; kb < 16; ++kb) {
            uint2 wb = g_wfrag[(F_P2 + nb * 16 + kb) * 32 + lane];
            #pragma unroll
            for (int mb = 0; mb < 4; ++mb) {
                int row = mb * 16;
                uint32_t a0 = sUw[(row + r)     * 132 + kb * 8 + q];
                uint32_t a1 = sUw[(row + r + 8) * 132 + kb * 8 + q];
                uint32_t a2 = sUw[(row + r)     * 132 + kb * 8 + 4 + q];
                uint32_t a3 = sUw[(row + r + 8) * 132 + kb * 8 + 4 + q];
                mma16816(acc[mb], a0, a1, a2, a3, wb.x, wb.y);
            }
        }
        float bj0 = p2_b[nb * 8 + 2 * q], bj1 = p2_b[nb * 8 + 2 * q + 1];
        int j = nb * 8 + 2 * q;
        float* og = out + (size_t)b * 4096;
        #pragma unroll
        for (int mb = 0; mb < 4; ++mb) {
            int tok = mb * 16 + r;
            float2 r0 = *(float2*)&sXf[tok * 64 + j];
            float2 r1 = *(float2*)&sXf[(tok + 8) * 64 + j];
            float2 o0, o1;
            o0.x = r0.x + acc[mb][0] + bj0;
            o0.y = r0.y + acc[mb][1] + bj1;
            o1.x = r1.x + acc[mb][2] + bj0;
            o1.y = r1.y + acc[mb][3] + bj1;
            *(float2*)&og[tok * 64 + j]       = o0;
            *(float2*)&og[(tok + 8) * 64 + j] = o1;
        }
    }
}

extern "C" void kernel_launch(void* const* d_in, const int* in_sizes, int n_in,
                              void* d_out, int out_size)
{
    const float* x      = (const float*)d_in[0];
    const float* ln1_g  = (const float*)d_in[1];
    const float* ln1_b  = (const float*)d_in[2];
    const float* qkv_w  = (const float*)d_in[3];
    const float* qkv_b  = (const float*)d_in[4];
    const float* proj_w = (const float*)d_in[5];
    const float* proj_b = (const float*)d_in[6];
    const float* ln2_g  = (const float*)d_in[7];
    const float* ln2_b  = (const float*)d_in[8];
    const float* fc_w   = (const float*)d_in[9];
    const float* fc_b   = (const float*)d_in[10];
    const float* p2_w   = (const float*)d_in[11];
    const float* p2_b   = (const float*)d_in[12];
    float* out = (float*)d_out;

    int B = in_sizes[0] / 4096;   // 4096

    convert_weights<<<192, 256>>>(qkv_w, proj_w, fc_w, p2_w);

    cudaFuncSetAttribute(block_kernel,
                         cudaFuncAttributeMaxDynamicSharedMemorySize, SMEM_BYTES);
    block_kernel<<<B, 256, SMEM_BYTES>>>(
        x, ln1_g, ln1_b, qkv_b, proj_b, ln2_g, ln2_b, fc_b, p2_b, out);
}

// round 3
// speedup vs baseline: 6.8903x; 1.1069x over previous
#include <cuda_runtime.h>
#include <cuda_bf16.h>
#include <math.h>
#include <stdint.h>

// Transformer block B=4096, T=64, C=64, H=4, hd=16.
// bf16 mma.sync tensor-core path; ldmatrix A-fragments; fp32 LN/softmax/residual.

#define EPS 1e-5f

// ---- fragment-ordered weight buffer (bf16), filled by pre-kernel ----
#define F_QKV  0      // 24 nb * 4 kb  = 96
#define F_PROJ 96     //  8 * 4        = 32
#define F_FC   128    // 32 * 4        = 128
#define F_P2   256    //  8 * 16       = 128
#define N_FRAGS 384
__device__ uint2 g_wfrag[N_FRAGS * 32];

__global__ void convert_weights(const float* __restrict__ qkv_w,
                                const float* __restrict__ proj_w,
                                const float* __restrict__ fc_w,
                                const float* __restrict__ p2_w)
{
    int e = blockIdx.x * blockDim.x + threadIdx.x;
    const float* W; int K, N, base;
    if (e < 12288)      { W = qkv_w;  K = 64;  N = 192; base = F_QKV; }
    else if (e < 16384) { W = proj_w; K = 64;  N = 64;  base = F_PROJ; e -= 12288; }
    else if (e < 32768) { W = fc_w;   K = 64;  N = 256; base = F_FC;   e -= 16384; }
    else if (e < 49152) { W = p2_w;   K = 256; N = 64;  base = F_P2;   e -= 32768; }
    else return;
    int k = e / N, n = e % N;
    int nb = n >> 3, kb = k >> 4, kr = k & 15;
    int lane = (n & 7) * 4 + ((kr & 7) >> 1);
    int reg  = kr >> 3;
    int half = kr & 1;
    int KB = K >> 4;
    __nv_bfloat16 v = __float2bfloat16(W[k * N + n]);
    unsigned short* dst = (unsigned short*)g_wfrag;
    dst[(((base + nb * KB + kb) * 32 + lane) * 2 + reg) * 2 + half] =
        *(unsigned short*)&v;
}

// ---- helpers ----
__device__ __forceinline__ void mma16816(float c[4],
    uint32_t a0, uint32_t a1, uint32_t a2, uint32_t a3,
    uint32_t b0, uint32_t b1)
{
    asm volatile(
        "mma.sync.aligned.m16n8k16.row.col.f32.bf16.bf16.f32 "
        "{%0,%1,%2,%3}, {%4,%5,%6,%7}, {%8,%9}, {%0,%1,%2,%3};\n"
        : "+f"(c[0]), "+f"(c[1]), "+f"(c[2]), "+f"(c[3])
        : "r"(a0), "r"(a1), "r"(a2), "r"(a3), "r"(b0), "r"(b1));
}

__device__ __forceinline__ void ldsm_x4(uint32_t a[4], uint32_t saddr) {
    asm volatile("ldmatrix.sync.aligned.m8n8.x4.shared.b16 {%0,%1,%2,%3}, [%4];"
        : "=r"(a[0]), "=r"(a[1]), "=r"(a[2]), "=r"(a[3]) : "r"(saddr));
}

__device__ __forceinline__ uint32_t smem_u32(const void* p) {
    return (uint32_t)__cvta_generic_to_shared(p);
}

__device__ __forceinline__ uint32_t pack_bf16(float lo, float hi) {
    __nv_bfloat162 h = __floats2bfloat162_rn(lo, hi);
    return *(uint32_t*)&h;
}

__device__ __forceinline__ float gelu_fast(float v) {
    // tanh-form gelu; |error| vs exact erf form < 1e-5 for |v| < 1
    float u = 0.7978845608028654f * v * (1.0f + 0.044715f * v * v);
    float e = __expf(2.0f * u);
    return 0.5f * v * (2.0f - __fdividef(2.0f, e + 1.0f));
}

// layernorm of fp32 [64x64] -> bf16 [64 x stride72]
__device__ __forceinline__ void layer_norm_bf16(
    const float* __restrict__ src, __nv_bfloat16* __restrict__ dst,
    const float* __restrict__ g, const float* __restrict__ bb,
    int lane, int warp)
{
    float g0 = g[lane], g1 = g[lane + 32];
    float b0 = bb[lane], b1 = bb[lane + 32];
    for (int t = warp; t < 64; t += 8) {
        float v0 = src[t * 64 + lane];
        float v1 = src[t * 64 + lane + 32];
        float s = v0 + v1;
        #pragma unroll
        for (int o = 16; o > 0; o >>= 1) s += __shfl_xor_sync(0xffffffffu, s, o);
        float mu = s * (1.0f / 64.0f);
        float d0 = v0 - mu, d1 = v1 - mu;
        float vs = d0 * d0 + d1 * d1;
        #pragma unroll
        for (int o = 16; o > 0; o >>= 1) vs += __shfl_xor_sync(0xffffffffu, vs, o);
        float rr = rsqrtf(vs * (1.0f / 64.0f) + EPS);
        dst[t * 72 + lane]      = __float2bfloat16(d0 * rr * g0 + b0);
        dst[t * 72 + lane + 32] = __float2bfloat16(d1 * rr * g1 + b1);
    }
}

// SMEM layout (bytes):
//   sXf  fp32 [64*64]                    @ 0      (16384)
//   sU   bf16 union:                     @ 16384  (33792)
//        qkv  [64 x 200] bf16 (100 words): Q words 0..31, K 32..63, V^T 64..99
//        gelu [64 x 264] bf16 (132 words)
//   sA   bf16 [64 x 72]                  @ 50176  (9216)   LN output
//   sY   bf16 [64 x 72]                  @ 59392  (9216)   attn output
#define SMEM_BYTES 68608

__global__ __launch_bounds__(256, 3) void block_kernel(
    const float* __restrict__ x,
    const float* __restrict__ ln1_g, const float* __restrict__ ln1_b,
    const float* __restrict__ qkv_b, const float* __restrict__ proj_b,
    const float* __restrict__ ln2_g, const float* __restrict__ ln2_b,
    const float* __restrict__ fc_b,  const float* __restrict__ p2_b,
    float* __restrict__ out)
{
    extern __shared__ char smem[];
    float* sXf = (float*)smem;
    __nv_bfloat16* sU = (__nv_bfloat16*)(smem + 16384);
    __nv_bfloat16* sA = (__nv_bfloat16*)(smem + 50176);
    __nv_bfloat16* sY = (__nv_bfloat16*)(smem + 59392);
    uint32_t* sUw = (uint32_t*)sU;
    uint32_t* sYw = (uint32_t*)sY;

    const int b = blockIdx.x, tid = threadIdx.x;
    const int lane = tid & 31, warp = tid >> 5;
    const int r = lane >> 2, q = lane & 3;

    const uint32_t uA = smem_u32(sA);
    const uint32_t uU = smem_u32(sU);
    const uint32_t uY = smem_u32(sY);
    // ldmatrix per-lane offsets: tile t = lane>>3
    const int ldrow = ((lane >> 3) & 1) * 8 + (lane & 7);
    const int ldwrd = (lane >> 4) * 4;

    // ---- load x tile ----
    {
        const float4* xg = (const float4*)(x + (size_t)b * 4096);
        float4* s4 = (float4*)sXf;
        #pragma unroll
        for (int i = tid; i < 1024; i += 256) s4[i] = xg[i];
    }
    __syncthreads();

    // ---- LN1 ----
    layer_norm_bf16(sXf, sA, ln1_g, ln1_b, lane, warp);
    __syncthreads();

    // ---- qkv GEMM: sA[64x64] @ W[64x192] + b ----
    // s=0 -> Q (scaled by 0.25), s=1 -> K, s=2 -> V stored TRANSPOSED
    #pragma unroll
    for (int s = 0; s < 3; ++s) {
        int nb = warp + s * 8;
        float acc[4][4] = {};
        #pragma unroll
        for (int kb = 0; kb < 4; ++kb) {
            uint2 wb = g_wfrag[(F_QKV + nb * 4 + kb) * 32 + lane];
            #pragma unroll
            for (int mb = 0; mb < 4; ++mb) {
                uint32_t Af[4];
                ldsm_x4(Af, uA + (((mb * 16 + ldrow) * 36 + kb * 8 + ldwrd) << 2));
                mma16816(acc[mb], Af[0], Af[1], Af[2], Af[3], wb.x, wb.y);
            }
        }
        float bj0 = qkv_b[nb * 8 + 2 * q], bj1 = qkv_b[nb * 8 + 2 * q + 1];
        if (s < 2) {
            float scl = (s == 0) ? 0.25f : 1.0f;  // fold 1/sqrt(hd) into Q (exact pow2)
            #pragma unroll
            for (int mb = 0; mb < 4; ++mb) {
                int tok = mb * 16 + r;
                sUw[tok * 100 + nb * 4 + q] =
                    pack_bf16((acc[mb][0] + bj0) * scl, (acc[mb][1] + bj1) * scl);
                sUw[(tok + 8) * 100 + nb * 4 + q] =
                    pack_bf16((acc[mb][2] + bj0) * scl, (acc[mb][3] + bj1) * scl);
            }
        } else {
            // V^T: dim dv = col-128 -> row dv, token -> halfword col 128+tok
            int dv = warp * 8 + 2 * q;
            #pragma unroll
            for (int mb = 0; mb < 4; ++mb) {
                int tok = mb * 16 + r;
                sU[dv * 200 + 128 + tok]           = __float2bfloat16(acc[mb][0] + bj0);
                sU[(dv + 1) * 200 + 128 + tok]     = __float2bfloat16(acc[mb][1] + bj1);
                sU[dv * 200 + 128 + tok + 8]       = __float2bfloat16(acc[mb][2] + bj0);
                sU[(dv + 1) * 200 + 128 + tok + 8] = __float2bfloat16(acc[mb][3] + bj1);
            }
        }
    }
    __syncthreads();

    // ---- attention: 16 (head,mb) blocks; balanced 2 per warp ----
    #pragma unroll
    for (int it = 0; it < 2; ++it) {
        int h  = (it == 0) ? (warp >> 2)      : 2 + (warp >> 2);
        int mb = (it == 0) ? (warp & 3)       : 3 - (warp & 3);
        int row0 = mb * 16;
        int nlim = 2 * mb + 1;      // causal: key blocks nb <= nlim

        uint32_t Qf[4];
        ldsm_x4(Qf, uU + (((row0 + ldrow) * 100 + 8 * h + ldwrd) << 2));

        float sc[8][4];
        #pragma unroll
        for (int nb = 0; nb < 8; ++nb) if (nb <= nlim) {
            sc[nb][0] = sc[nb][1] = sc[nb][2] = sc[nb][3] = 0.0f;
            int tk = nb * 8 + r;
            uint32_t kb0 = sUw[tk * 100 + 32 + 8 * h + q];
            uint32_t kb1 = sUw[tk * 100 + 32 + 8 * h + 4 + q];
            mma16816(sc[nb], Qf[0], Qf[1], Qf[2], Qf[3], kb0, kb1);
        }

        int qi0 = row0 + r, qi1 = qi0 + 8;
        float m0 = -1e30f, m1 = -1e30f;
        #pragma unroll
        for (int nb = 0; nb < 8; ++nb) if (nb <= nlim)
            #pragma unroll
            for (int cc = 0; cc < 2; ++cc) {
                int kj = nb * 8 + 2 * q + cc;
                float v0 = (kj <= qi0) ? sc[nb][cc]     : -1e30f;
                float v1 = (kj <= qi1) ? sc[nb][2 + cc] : -1e30f;
                sc[nb][cc] = v0; sc[nb][2 + cc] = v1;
                m0 = fmaxf(m0, v0); m1 = fmaxf(m1, v1);
            }
        m0 = fmaxf(m0, __shfl_xor_sync(0xffffffffu, m0, 1));
        m0 = fmaxf(m0, __shfl_xor_sync(0xffffffffu, m0, 2));
        m1 = fmaxf(m1, __shfl_xor_sync(0xffffffffu, m1, 1));
        m1 = fmaxf(m1, __shfl_xor_sync(0xffffffffu, m1, 2));

        float l0 = 0.0f, l1 = 0.0f;
        #pragma unroll
        for (int nb = 0; nb < 8; ++nb) if (nb <= nlim)
            #pragma unroll
            for (int cc = 0; cc < 2; ++cc) {
                float p0 = __expf(sc[nb][cc] - m0);
                float p1 = __expf(sc[nb][2 + cc] - m1);
                sc[nb][cc] = p0; sc[nb][2 + cc] = p1;
                l0 += p0; l1 += p1;
            }
        l0 += __shfl_xor_sync(0xffffffffu, l0, 1);
        l0 += __shfl_xor_sync(0xffffffffu, l0, 2);
        l1 += __shfl_xor_sync(0xffffffffu, l1, 1);
        l1 += __shfl_xor_sync(0xffffffffu, l1, 2);

        // P -> A fragments in registers (only needed kb <= mb)
        uint32_t Pf[4][4];
        #pragma unroll
        for (int kb = 0; kb < 4; ++kb) if (kb <= mb) {
            Pf[kb][0] = pack_bf16(sc[2 * kb][0],     sc[2 * kb][1]);
            Pf[kb][1] = pack_bf16(sc[2 * kb][2],     sc[2 * kb][3]);
            Pf[kb][2] = pack_bf16(sc[2 * kb + 1][0], sc[2 * kb + 1][1]);
            Pf[kb][3] = pack_bf16(sc[2 * kb + 1][2], sc[2 * kb + 1][3]);
        }

        // y = P @ V via V^T rows (32-bit coalesced B fragments)
        float y0[4] = {}, y1[4] = {};
        #pragma unroll
        for (int kb = 0; kb < 4; ++kb) if (kb <= mb) {
            #pragma unroll
            for (int nbd = 0; nbd < 2; ++nbd) {
                int dv = 16 * h + 8 * nbd + r;
                uint32_t vb0 = sUw[dv * 100 + 64 + kb * 8 + q];
                uint32_t vb1 = sUw[dv * 100 + 64 + kb * 8 + 4 + q];
                mma16816(nbd ? y1 : y0, Pf[kb][0], Pf[kb][1], Pf[kb][2], Pf[kb][3],
                         vb0, vb1);
            }
        }
        float inv0 = 1.0f / l0, inv1 = 1.0f / l1;
        int tok = row0 + r;
        sYw[tok * 36 + 8 * h + q]           = pack_bf16(y0[0] * inv0, y0[1] * inv0);
        sYw[(tok + 8) * 36 + 8 * h + q]     = pack_bf16(y0[2] * inv1, y0[3] * inv1);
        sYw[tok * 36 + 8 * h + 4 + q]       = pack_bf16(y1[0] * inv0, y1[1] * inv0);
        sYw[(tok + 8) * 36 + 8 * h + 4 + q] = pack_bf16(y1[2] * inv1, y1[3] * inv1);
    }
    __syncthreads();

    // ---- attn proj + residual: sXf += sY @ W + b ----
    {
        int nb = warp;
        float acc[4][4] = {};
        #pragma unroll
        for (int kb = 0; kb < 4; ++kb) {
            uint2 wb = g_wfrag[(F_PROJ + nb * 4 + kb) * 32 + lane];
            #pragma unroll
            for (int mb = 0; mb < 4; ++mb) {
                uint32_t Af[4];
                ldsm_x4(Af, uY + (((mb * 16 + ldrow) * 36 + kb * 8 + ldwrd) << 2));
                mma16816(acc[mb], Af[0], Af[1], Af[2], Af[3], wb.x, wb.y);
            }
        }
        float bj0 = proj_b[nb * 8 + 2 * q], bj1 = proj_b[nb * 8 + 2 * q + 1];
        int j = nb * 8 + 2 * q;
        #pragma unroll
        for (int mb = 0; mb < 4; ++mb) {
            int tok = mb * 16 + r;
            sXf[tok * 64 + j]           += acc[mb][0] + bj0;
            sXf[tok * 64 + j + 1]       += acc[mb][1] + bj1;
            sXf[(tok + 8) * 64 + j]     += acc[mb][2] + bj0;
            sXf[(tok + 8) * 64 + j + 1] += acc[mb][3] + bj1;
        }
    }
    __syncthreads();

    // ---- LN2 ----
    layer_norm_bf16(sXf, sA, ln2_g, ln2_b, lane, warp);
    __syncthreads();

    // ---- fc GEMM + GELU -> sU gelu region (stride 132 words) ----
    #pragma unroll
    for (int s = 0; s < 4; ++s) {
        int nb = warp + s * 8;
        float acc[4][4] = {};
        #pragma unroll
        for (int kb = 0; kb < 4; ++kb) {
            uint2 wb = g_wfrag[(F_FC + nb * 4 + kb) * 32 + lane];
            #pragma unroll
            for (int mb = 0; mb < 4; ++mb) {
                uint32_t Af[4];
                ldsm_x4(Af, uA + (((mb * 16 + ldrow) * 36 + kb * 8 + ldwrd) << 2));
                mma16816(acc[mb], Af[0], Af[1], Af[2], Af[3], wb.x, wb.y);
            }
        }
        float bj0 = fc_b[nb * 8 + 2 * q], bj1 = fc_b[nb * 8 + 2 * q + 1];
        #pragma unroll
        for (int mb = 0; mb < 4; ++mb) {
            int tok = mb * 16 + r;
            sUw[tok * 132 + nb * 4 + q] = pack_bf16(
                gelu_fast(acc[mb][0] + bj0), gelu_fast(acc[mb][1] + bj1));
            sUw[(tok + 8) * 132 + nb * 4 + q] = pack_bf16(
                gelu_fast(acc[mb][2] + bj0), gelu_fast(acc[mb][3] + bj1));
        }
    }
    __syncthreads();

    // ---- mlp proj (K=256) + residual -> out ----
    {
        int nb = warp;
        float acc[4][4] = {};
        #pragma unroll
        for (int kb = 0; kb < 16; ++kb) {
            uint2 wb = g_wfrag[(F_P2 + nb * 16 + kb) * 32 + lane];
            #pragma unroll
            for (int mb = 0; mb < 4; ++mb) {
                uint32_t Af[4];
                ldsm_x4(Af, uU + (((mb * 16 + ldrow) * 132 + kb * 8 + ldwrd) << 2));
                mma16816(acc[mb], Af[0], Af[1], Af[2], Af[3], wb.x, wb.y);
            }
        }
        float bj0 = p2_b[nb * 8 + 2 * q], bj1 = p2_b[nb * 8 + 2 * q + 1];
        int j = nb * 8 + 2 * q;
        float* og = out + (size_t)b * 4096;
        #pragma unroll
        for (int mb = 0; mb < 4; ++mb) {
            int tok = mb * 16 + r;
            float2 r0 = *(float2*)&sXf[tok * 64 + j];
            float2 r1 = *(float2*)&sXf[(tok + 8) * 64 + j];
            float2 o0, o1;
            o0.x = r0.x + acc[mb][0] + bj0;
            o0.y = r0.y + acc[mb][1] + bj1;
            o1.x = r1.x + acc[mb][2] + bj0;
            o1.y = r1.y + acc[mb][3] + bj1;
            *(float2*)&og[tok * 64 + j]       = o0;
            *(float2*)&og[(tok + 8) * 64 + j] = o1;
        }
    }
}

extern "C" void kernel_launch(void* const* d_in, const int* in_sizes, int n_in,
                              void* d_out, int out_size)
{
    const float* x      = (const float*)d_in[0];
    const float* ln1_g  = (const float*)d_in[1];
    const float* ln1_b  = (const float*)d_in[2];
    const float* qkv_w  = (const float*)d_in[3];
    const float* qkv_b  = (const float*)d_in[4];
    const float* proj_w = (const float*)d_in[5];
    const float* proj_b = (const float*)d_in[6];
    const float* ln2_g  = (const float*)d_in[7];
    const float* ln2_b  = (const float*)d_in[8];
    const float* fc_w   = (const float*)d_in[9];
    const float* fc_b   = (const float*)d_in[10];
    const float* p2_w   = (const float*)d_in[11];
    const float* p2_b   = (const float*)d_in[12];
    float* out = (float*)d_out;

    int B = in_sizes[0] / 4096;   // 4096

    convert_weights<<<192, 256>>>(qkv_w, proj_w, fc_w, p2_w);

    cudaFuncSetAttribute(block_kernel,
                         cudaFuncAttributeMaxDynamicSharedMemorySize, SMEM_BYTES);
    block_kernel<<<B, 256, SMEM_BYTES>>>(
        x, ln1_g, ln1_b, qkv_b, proj_b, ln2_g, ln2_b, fc_b, p2_b, out);
}

// round 4
// speedup vs baseline: 7.9619x; 1.1555x over previous
#include <cuda_runtime.h>
#include <cuda_bf16.h>
#include <math.h>
#include <stdint.h>

// Transformer block B=4096, T=64, C=64, H=4, hd=16.
// bf16 mma.sync; register-cached W fragments; A-fragment reuse; fp32 LN/softmax.

#define EPS 1e-5f

#define F_QKV  0
#define F_PROJ 96
#define F_FC   128
#define F_P2   256
#define N_FRAGS 384
__device__ uint2 g_wfrag[N_FRAGS * 32];

__global__ void convert_weights(const float* __restrict__ qkv_w,
                                const float* __restrict__ proj_w,
                                const float* __restrict__ fc_w,
                                const float* __restrict__ p2_w)
{
    int e = blockIdx.x * blockDim.x + threadIdx.x;
    const float* W; int K, N, base;
    if (e < 12288)      { W = qkv_w;  K = 64;  N = 192; base = F_QKV; }
    else if (e < 16384) { W = proj_w; K = 64;  N = 64;  base = F_PROJ; e -= 12288; }
    else if (e < 32768) { W = fc_w;   K = 64;  N = 256; base = F_FC;   e -= 16384; }
    else if (e < 49152) { W = p2_w;   K = 256; N = 64;  base = F_P2;   e -= 32768; }
    else return;
    int k = e / N, n = e % N;
    int nb = n >> 3, kb = k >> 4, kr = k & 15;
    int lane = (n & 7) * 4 + ((kr & 7) >> 1);
    int reg  = kr >> 3;
    int half = kr & 1;
    int KB = K >> 4;
    __nv_bfloat16 v = __float2bfloat16(W[k * N + n]);
    unsigned short* dst = (unsigned short*)g_wfrag;
    dst[(((base + nb * KB + kb) * 32 + lane) * 2 + reg) * 2 + half] =
        *(unsigned short*)&v;
}

__device__ __forceinline__ void mma16816(float c[4],
    uint32_t a0, uint32_t a1, uint32_t a2, uint32_t a3,
    uint32_t b0, uint32_t b1)
{
    asm volatile(
        "mma.sync.aligned.m16n8k16.row.col.f32.bf16.bf16.f32 "
        "{%0,%1,%2,%3}, {%4,%5,%6,%7}, {%8,%9}, {%0,%1,%2,%3};\n"
        : "+f"(c[0]), "+f"(c[1]), "+f"(c[2]), "+f"(c[3])
        : "r"(a0), "r"(a1), "r"(a2), "r"(a3), "r"(b0), "r"(b1));
}

__device__ __forceinline__ void ldsm_x4(uint32_t a[4], uint32_t saddr) {
    asm volatile("ldmatrix.sync.aligned.m8n8.x4.shared.b16 {%0,%1,%2,%3}, [%4];"
        : "=r"(a[0]), "=r"(a[1]), "=r"(a[2]), "=r"(a[3]) : "r"(saddr));
}

__device__ __forceinline__ uint32_t smem_u32(const void* p) {
    return (uint32_t)__cvta_generic_to_shared(p);
}

__device__ __forceinline__ uint32_t pack_bf16(float lo, float hi) {
    __nv_bfloat162 h = __floats2bfloat162_rn(lo, hi);
    return *(uint32_t*)&h;
}

__device__ __forceinline__ float gelu_fast(float v) {
    float u = 0.7978845608028654f * v * (1.0f + 0.044715f * v * v);
    float e = __expf(2.0f * u);
    return 0.5f * v * (2.0f - __fdividef(2.0f, e + 1.0f));
}

__device__ __forceinline__ void layer_norm_bf16(
    const float* __restrict__ src, __nv_bfloat16* __restrict__ dst,
    const float* __restrict__ g, const float* __restrict__ bb,
    int lane, int warp)
{
    float g0 = g[lane], g1 = g[lane + 32];
    float b0 = bb[lane], b1 = bb[lane + 32];
    for (int t = warp; t < 64; t += 8) {
        float v0 = src[t * 64 + lane];
        float v1 = src[t * 64 + lane + 32];
        float s = v0 + v1;
        #pragma unroll
        for (int o = 16; o > 0; o >>= 1) s += __shfl_xor_sync(0xffffffffu, s, o);
        float mu = s * (1.0f / 64.0f);
        float d0 = v0 - mu, d1 = v1 - mu;
        float vs = d0 * d0 + d1 * d1;
        #pragma unroll
        for (int o = 16; o > 0; o >>= 1) vs += __shfl_xor_sync(0xffffffffu, vs, o);
        float rr = rsqrtf(vs * (1.0f / 64.0f) + EPS);
        dst[t * 72 + lane]      = __float2bfloat16(d0 * rr * g0 + b0);
        dst[t * 72 + lane + 32] = __float2bfloat16(d1 * rr * g1 + b1);
    }
}

// SMEM layout (bytes): sXf fp32 @0 (16384); sU bf16 @16384 (33792)
//   qkv [64x200]: Q words 0..31, K 32..63, V^T 64..99 ; gelu [64x264]
// sA bf16 [64x72] @50176 ; sY bf16 [64x72] @59392
#define SMEM_BYTES 68608

__global__ __launch_bounds__(256, 3) void block_kernel(
    const float* __restrict__ x,
    const float* __restrict__ ln1_g, const float* __restrict__ ln1_b,
    const float* __restrict__ qkv_b, const float* __restrict__ proj_b,
    const float* __restrict__ ln2_g, const float* __restrict__ ln2_b,
    const float* __restrict__ fc_b,  const float* __restrict__ p2_b,
    float* __restrict__ out)
{
    extern __shared__ char smem[];
    float* sXf = (float*)smem;
    __nv_bfloat16* sU = (__nv_bfloat16*)(smem + 16384);
    __nv_bfloat16* sA = (__nv_bfloat16*)(smem + 50176);
    __nv_bfloat16* sY = (__nv_bfloat16*)(smem + 59392);
    uint32_t* sUw = (uint32_t*)sU;
    uint32_t* sYw = (uint32_t*)sY;

    const int b = blockIdx.x, tid = threadIdx.x;
    const int lane = tid & 31, warp = tid >> 5;
    const int r = lane >> 2, q = lane & 3;

    const uint32_t uA = smem_u32(sA);
    const uint32_t uU = smem_u32(sU);
    const uint32_t uY = smem_u32(sY);
    const int ldrow = ((lane >> 3) & 1) * 8 + (lane & 7);
    const int ldwrd = (lane >> 4) * 4;

    // ---- load x tile ----
    {
        const float4* xg = (const float4*)(x + (size_t)b * 4096);
        float4* s4 = (float4*)sXf;
        #pragma unroll
        for (int i = tid; i < 1024; i += 256) s4[i] = xg[i];
    }
    __syncthreads();

    // ---- LN1 ----
    layer_norm_bf16(sXf, sA, ln1_g, ln1_b, lane, warp);
    __syncthreads();

    // ---- qkv GEMM: W cached in regs, A loaded once per mb ----
    {
        uint2 wq[3][4];
        float bq[3][2];
        #pragma unroll
        for (int s = 0; s < 3; ++s) {
            #pragma unroll
            for (int kb = 0; kb < 4; ++kb)
                wq[s][kb] = g_wfrag[(F_QKV + (warp + s * 8) * 4 + kb) * 32 + lane];
            bq[s][0] = qkv_b[(warp + s * 8) * 8 + 2 * q];
            bq[s][1] = qkv_b[(warp + s * 8) * 8 + 2 * q + 1];
        }
        #pragma unroll
        for (int mb = 0; mb < 4; ++mb) {
            uint32_t Af[4][4];
            #pragma unroll
            for (int kb = 0; kb < 4; ++kb)
                ldsm_x4(Af[kb], uA + (((mb * 16 + ldrow) * 36 + kb * 8 + ldwrd) << 2));
            int tok = mb * 16 + r;
            #pragma unroll
            for (int s = 0; s < 3; ++s) {
                float acc[4] = {};
                #pragma unroll
                for (int kb = 0; kb < 4; ++kb)
                    mma16816(acc, Af[kb][0], Af[kb][1], Af[kb][2], Af[kb][3],
                             wq[s][kb].x, wq[s][kb].y);
                if (s == 0) {       // Q, scaled by 1/sqrt(hd)=0.25 (exact pow2)
                    sUw[tok * 100 + warp * 4 + q] =
                        pack_bf16((acc[0] + bq[0][0]) * 0.25f, (acc[1] + bq[0][1]) * 0.25f);
                    sUw[(tok + 8) * 100 + warp * 4 + q] =
                        pack_bf16((acc[2] + bq[0][0]) * 0.25f, (acc[3] + bq[0][1]) * 0.25f);
                } else if (s == 1) { // K
                    sUw[tok * 100 + 32 + warp * 4 + q] =
                        pack_bf16(acc[0] + bq[1][0], acc[1] + bq[1][1]);
                    sUw[(tok + 8) * 100 + 32 + warp * 4 + q] =
                        pack_bf16(acc[2] + bq[1][0], acc[3] + bq[1][1]);
                } else {             // V stored transposed
                    int dv = warp * 8 + 2 * q;
                    sU[dv * 200 + 128 + tok]           = __float2bfloat16(acc[0] + bq[2][0]);
                    sU[(dv + 1) * 200 + 128 + tok]     = __float2bfloat16(acc[1] + bq[2][1]);
                    sU[dv * 200 + 128 + tok + 8]       = __float2bfloat16(acc[2] + bq[2][0]);
                    sU[(dv + 1) * 200 + 128 + tok + 8] = __float2bfloat16(acc[3] + bq[2][1]);
                }
            }
        }
    }
    __syncthreads();

    // ---- attention: 16 (head,mb) blocks; balanced 2 per warp ----
    #pragma unroll
    for (int it = 0; it < 2; ++it) {
        int h  = (it == 0) ? (warp >> 2) : 2 + (warp >> 2);
        int mb = (it == 0) ? (warp & 3)  : 3 - (warp & 3);
        int row0 = mb * 16;
        int nlim = 2 * mb + 1;

        uint32_t Qf[4];
        ldsm_x4(Qf, uU + (((row0 + ldrow) * 100 + 8 * h + ldwrd) << 2));

        float sc[8][4];
        #pragma unroll
        for (int nb = 0; nb < 8; ++nb) if (nb <= nlim) {
            sc[nb][0] = sc[nb][1] = sc[nb][2] = sc[nb][3] = 0.0f;
            int tk = nb * 8 + r;
            uint32_t kb0 = sUw[tk * 100 + 32 + 8 * h + q];
            uint32_t kb1 = sUw[tk * 100 + 32 + 8 * h + 4 + q];
            mma16816(sc[nb], Qf[0], Qf[1], Qf[2], Qf[3], kb0, kb1);
        }

        int qi0 = row0 + r, qi1 = qi0 + 8;
        float m0 = -1e30f, m1 = -1e30f;
        #pragma unroll
        for (int nb = 0; nb < 8; ++nb) if (nb <= nlim)
            #pragma unroll
            for (int cc = 0; cc < 2; ++cc) {
                int kj = nb * 8 + 2 * q + cc;
                float v0 = (kj <= qi0) ? sc[nb][cc]     : -1e30f;
                float v1 = (kj <= qi1) ? sc[nb][2 + cc] : -1e30f;
                sc[nb][cc] = v0; sc[nb][2 + cc] = v1;
                m0 = fmaxf(m0, v0); m1 = fmaxf(m1, v1);
            }
        m0 = fmaxf(m0, __shfl_xor_sync(0xffffffffu, m0, 1));
        m0 = fmaxf(m0, __shfl_xor_sync(0xffffffffu, m0, 2));
        m1 = fmaxf(m1, __shfl_xor_sync(0xffffffffu, m1, 1));
        m1 = fmaxf(m1, __shfl_xor_sync(0xffffffffu, m1, 2));

        float l0 = 0.0f, l1 = 0.0f;
        #pragma unroll
        for (int nb = 0; nb < 8; ++nb) if (nb <= nlim)
            #pragma unroll
            for (int cc = 0; cc < 2; ++cc) {
                float p0 = __expf(sc[nb][cc] - m0);
                float p1 = __expf(sc[nb][2 + cc] - m1);
                sc[nb][cc] = p0; sc[nb][2 + cc] = p1;
                l0 += p0; l1 += p1;
            }
        l0 += __shfl_xor_sync(0xffffffffu, l0, 1);
        l0 += __shfl_xor_sync(0xffffffffu, l0, 2);
        l1 += __shfl_xor_sync(0xffffffffu, l1, 1);
        l1 += __shfl_xor_sync(0xffffffffu, l1, 2);

        uint32_t Pf[4][4];
        #pragma unroll
        for (int kb = 0; kb < 4; ++kb) if (kb <= mb) {
            Pf[kb][0] = pack_bf16(sc[2 * kb][0],     sc[2 * kb][1]);
            Pf[kb][1] = pack_bf16(sc[2 * kb][2],     sc[2 * kb][3]);
            Pf[kb][2] = pack_bf16(sc[2 * kb + 1][0], sc[2 * kb + 1][1]);
            Pf[kb][3] = pack_bf16(sc[2 * kb + 1][2], sc[2 * kb + 1][3]);
        }

        float y0[4] = {}, y1[4] = {};
        #pragma unroll
        for (int kb = 0; kb < 4; ++kb) if (kb <= mb) {
            #pragma unroll
            for (int nbd = 0; nbd < 2; ++nbd) {
                int dv = 16 * h + 8 * nbd + r;
                uint32_t vb0 = sUw[dv * 100 + 64 + kb * 8 + q];
                uint32_t vb1 = sUw[dv * 100 + 64 + kb * 8 + 4 + q];
                mma16816(nbd ? y1 : y0, Pf[kb][0], Pf[kb][1], Pf[kb][2], Pf[kb][3],
                         vb0, vb1);
            }
        }
        float inv0 = 1.0f / l0, inv1 = 1.0f / l1;
        int tok = row0 + r;
        sYw[tok * 36 + 8 * h + q]           = pack_bf16(y0[0] * inv0, y0[1] * inv0);
        sYw[(tok + 8) * 36 + 8 * h + q]     = pack_bf16(y0[2] * inv1, y0[3] * inv1);
        sYw[tok * 36 + 8 * h + 4 + q]       = pack_bf16(y1[0] * inv0, y1[1] * inv0);
        sYw[(tok + 8) * 36 + 8 * h + 4 + q] = pack_bf16(y1[2] * inv1, y1[3] * inv1);
    }
    __syncthreads();

    // ---- attn proj + residual: 2mb x 2nb per warp ----
    {
        int mbh = warp >> 2, nbh = warp & 3;
        uint2 wp[2][4];
        #pragma unroll
        for (int nbi = 0; nbi < 2; ++nbi)
            #pragma unroll
            for (int kb = 0; kb < 4; ++kb)
                wp[nbi][kb] = g_wfrag[(F_PROJ + (nbh * 2 + nbi) * 4 + kb) * 32 + lane];
        float acc[2][2][4] = {};
        #pragma unroll
        for (int mbi = 0; mbi < 2; ++mbi) {
            uint32_t Af[4][4];
            #pragma unroll
            for (int kb = 0; kb < 4; ++kb)
                ldsm_x4(Af[kb], uY + ((((mbh * 2 + mbi) * 16 + ldrow) * 36 + kb * 8 + ldwrd) << 2));
            #pragma unroll
            for (int nbi = 0; nbi < 2; ++nbi)
                #pragma unroll
                for (int kb = 0; kb < 4; ++kb)
                    mma16816(acc[mbi][nbi], Af[kb][0], Af[kb][1], Af[kb][2], Af[kb][3],
                             wp[nbi][kb].x, wp[nbi][kb].y);
        }
        #pragma unroll
        for (int mbi = 0; mbi < 2; ++mbi)
            #pragma unroll
            for (int nbi = 0; nbi < 2; ++nbi) {
                int j = (nbh * 2 + nbi) * 8 + 2 * q;
                int tok = (mbh * 2 + mbi) * 16 + r;
                float bj0 = proj_b[j], bj1 = proj_b[j + 1];
                sXf[tok * 64 + j]           += acc[mbi][nbi][0] + bj0;
                sXf[tok * 64 + j + 1]       += acc[mbi][nbi][1] + bj1;
                sXf[(tok + 8) * 64 + j]     += acc[mbi][nbi][2] + bj0;
                sXf[(tok + 8) * 64 + j + 1] += acc[mbi][nbi][3] + bj1;
            }
    }
    __syncthreads();

    // ---- LN2 ----
    layer_norm_bf16(sXf, sA, ln2_g, ln2_b, lane, warp);
    __syncthreads();

    // ---- fc GEMM + GELU: W cached (16 frags), A loaded once per mb ----
    {
        uint2 wf[4][4];
        float bf[4][2];
        #pragma unroll
        for (int s = 0; s < 4; ++s) {
            #pragma unroll
            for (int kb = 0; kb < 4; ++kb)
                wf[s][kb] = g_wfrag[(F_FC + (warp + s * 8) * 4 + kb) * 32 + lane];
            bf[s][0] = fc_b[(warp + s * 8) * 8 + 2 * q];
            bf[s][1] = fc_b[(warp + s * 8) * 8 + 2 * q + 1];
        }
        #pragma unroll
        for (int mb = 0; mb < 4; ++mb) {
            uint32_t Af[4][4];
            #pragma unroll
            for (int kb = 0; kb < 4; ++kb)
                ldsm_x4(Af[kb], uA + (((mb * 16 + ldrow) * 36 + kb * 8 + ldwrd) << 2));
            int tok = mb * 16 + r;
            #pragma unroll
            for (int s = 0; s < 4; ++s) {
                float acc[4] = {};
                #pragma unroll
                for (int kb = 0; kb < 4; ++kb)
                    mma16816(acc, Af[kb][0], Af[kb][1], Af[kb][2], Af[kb][3],
                             wf[s][kb].x, wf[s][kb].y);
                int nb = warp + s * 8;
                sUw[tok * 132 + nb * 4 + q] = pack_bf16(
                    gelu_fast(acc[0] + bf[s][0]), gelu_fast(acc[1] + bf[s][1]));
                sUw[(tok + 8) * 132 + nb * 4 + q] = pack_bf16(
                    gelu_fast(acc[2] + bf[s][0]), gelu_fast(acc[3] + bf[s][1]));
            }
        }
    }
    __syncthreads();

    // ---- mlp proj (K=256) + residual -> out: 2mb x 2nb per warp ----
    {
        int mbh = warp >> 2, nbh = warp & 3;
        float acc[2][2][4] = {};
        #pragma unroll
        for (int kb = 0; kb < 16; ++kb) {
            uint32_t A0[4], A1[4];
            ldsm_x4(A0, uU + ((((mbh * 2) * 16 + ldrow) * 132 + kb * 8 + ldwrd) << 2));
            ldsm_x4(A1, uU + ((((mbh * 2 + 1) * 16 + ldrow) * 132 + kb * 8 + ldwrd) << 2));
            uint2 w0 = g_wfrag[(F_P2 + (nbh * 2) * 16 + kb) * 32 + lane];
            uint2 w1 = g_wfrag[(F_P2 + (nbh * 2 + 1) * 16 + kb) * 32 + lane];
            mma16816(acc[0][0], A0[0], A0[1], A0[2], A0[3], w0.x, w0.y);
            mma16816(acc[0][1], A0[0], A0[1], A0[2], A0[3], w1.x, w1.y);
            mma16816(acc[1][0], A1[0], A1[1], A1[2], A1[3], w0.x, w0.y);
            mma16816(acc[1][1], A1[0], A1[1], A1[2], A1[3], w1.x, w1.y);
        }
        float* og = out + (size_t)b * 4096;
        #pragma unroll
        for (int mbi = 0; mbi < 2; ++mbi)
            #pragma unroll
            for (int nbi = 0; nbi < 2; ++nbi) {
                int j = (nbh * 2 + nbi) * 8 + 2 * q;
                int tok = (mbh * 2 + mbi) * 16 + r;
                float bj0 = p2_b[j], bj1 = p2_b[j + 1];
                float2 r0 = *(float2*)&sXf[tok * 64 + j];
                float2 r1 = *(float2*)&sXf[(tok + 8) * 64 + j];
                float2 o0, o1;
                o0.x = r0.x + acc[mbi][nbi][0] + bj0;
                o0.y = r0.y + acc[mbi][nbi][1] + bj1;
                o1.x = r1.x + acc[mbi][nbi][2] + bj0;
                o1.y = r1.y + acc[mbi][nbi][3] + bj1;
                *(float2*)&og[tok * 64 + j]       = o0;
                *(float2*)&og[(tok + 8) * 64 + j] = o1;
            }
    }
}

extern "C" void kernel_launch(void* const* d_in, const int* in_sizes, int n_in,
                              void* d_out, int out_size)
{
    const float* x      = (const float*)d_in[0];
    const float* ln1_g  = (const float*)d_in[1];
    const float* ln1_b  = (const float*)d_in[2];
    const float* qkv_w  = (const float*)d_in[3];
    const float* qkv_b  = (const float*)d_in[4];
    const float* proj_w = (const float*)d_in[5];
    const float* proj_b = (const float*)d_in[6];
    const float* ln2_g  = (const float*)d_in[7];
    const float* ln2_b  = (const float*)d_in[8];
    const float* fc_w   = (const float*)d_in[9];
    const float* fc_b   = (const float*)d_in[10];
    const float* p2_w   = (const float*)d_in[11];
    const float* p2_b   = (const float*)d_in[12];
    float* out = (float*)d_out;

    int B = in_sizes[0] / 4096;

    convert_weights<<<192, 256>>>(qkv_w, proj_w, fc_w, p2_w);

    cudaFuncSetAttribute(block_kernel,
                         cudaFuncAttributeMaxDynamicSharedMemorySize, SMEM_BYTES);
    block_kernel<<<B, 256, SMEM_BYTES>>>(
        x, ln1_g, ln1_b, qkv_b, proj_b, ln2_g, ln2_b, fc_b, p2_b, out);
}